// round 13
// baseline (speedup 1.0000x reference)
#include <cuda_runtime.h>

// 8-qubit statevector simulator, one warp per batch element.
// State: 256 complex amplitudes = 8 complex per lane, stored SoA-packed:
//   R[4], I[4] are f32x2 (64-bit) registers; R[k] = (re[2k], re[2k+1]).
// Global amplitude index i = lane*8 + j  (wire q <-> bit (7-q) of i):
//   wires 0..4 -> lane bits 4..0 (cross-lane, via shfl.xor)
//   wires 5,6  -> packed-register index bits 1,0 (k bits)
//   wire 7     -> low/high half of the f32x2 vector
// All gate math uses fma.rn.f32x2 (Blackwell packed fp32) -> halves FMA-pipe work.

namespace {

constexpr int NQ = 8;
constexpr int LAYERS = 6;
using ull = unsigned long long;

__device__ __forceinline__ ull pk(float lo, float hi) {
    ull r;
    asm("mov.b64 %0, {%1, %2};" : "=l"(r) : "r"(__float_as_uint(lo)), "r"(__float_as_uint(hi)));
    return r;
}
__device__ __forceinline__ void upk(ull v, float& lo, float& hi) {
    unsigned ul, uh;
    asm("mov.b64 {%0, %1}, %2;" : "=r"(ul), "=r"(uh) : "l"(v));
    lo = __uint_as_float(ul); hi = __uint_as_float(uh);
}
__device__ __forceinline__ ull bc(float s) { return pk(s, s); }
__device__ __forceinline__ ull vfma(ull a, ull b, ull c) {
    ull d;
    asm("fma.rn.f32x2 %0, %1, %2, %3;" : "=l"(d) : "l"(a), "l"(b), "l"(c));
    return d;
}
__device__ __forceinline__ ull vmul(ull a, ull b) {
    ull d;
    asm("mul.rn.f32x2 %0, %1, %2;" : "=l"(d) : "l"(a), "l"(b));
    return d;
}
template<int LB>
__device__ __forceinline__ ull shfl_u64(ull v) {
    float lo, hi; upk(v, lo, hi);
    lo = __shfl_xor_sync(0xffffffffu, lo, 1 << LB);
    hi = __shfl_xor_sync(0xffffffffu, hi, 1 << LB);
    return pk(lo, hi);
}
__device__ __forceinline__ ull dup_lo(ull v) { float lo, hi; upk(v, lo, hi); return pk(lo, lo); }
__device__ __forceinline__ ull dup_hi(ull v) { float lo, hi; upk(v, lo, hi); return pk(hi, hi); }
__device__ __forceinline__ ull swap_h(ull v) { float lo, hi; upk(v, lo, hi); return pk(hi, lo); }

__device__ __forceinline__ float2 cmul(float2 a, float2 b) {
    return make_float2(fmaf(a.x, b.x, -a.y * b.y), fmaf(a.x, b.y, a.y * b.x));
}

// Generic shared 2x2 gate on wire Q, packed state. U = {U00, U01, U10, U11}.
template<int Q>
__device__ __forceinline__ void apply_1q(ull (&R)[4], ull (&I)[4], int lane,
                                         const float2* __restrict__ U) {
    const float2 U00 = U[0], U01 = U[1], U10 = U[2], U11 = U[3];
    constexpr int BIT = 7 - Q;
    if constexpr (BIT >= 3) {
        // cross-lane wire (lane bit LB). new = A*mine + B*other
        constexpr int LB = BIT - 3;
        const bool b = (lane >> LB) & 1;
        float2 A, B;
        A.x = b ? U11.x : U00.x;  A.y = b ? U11.y : U00.y;
        B.x = b ? U10.x : U01.x;  B.y = b ? U10.y : U01.y;
        const ull Ax = bc(A.x), Ay = bc(A.y), nAy = bc(-A.y);
        const ull Bx = bc(B.x), By = bc(B.y), nBy = bc(-B.y);
        #pragma unroll
        for (int k = 0; k < 4; k++) {
            const ull oR = shfl_u64<LB>(R[k]);
            const ull oI = shfl_u64<LB>(I[k]);
            // n.re = A.x*s.re - A.y*s.im + B.x*o.re - B.y*o.im
            ull tR = vfma(Bx, oR, vmul(nBy, oI));
            tR = vfma(nAy, I[k], tR);
            const ull nR = vfma(Ax, R[k], tR);
            // n.im = A.x*s.im + A.y*s.re + B.x*o.im + B.y*o.re
            ull tI = vfma(Bx, oI, vmul(By, oR));
            tI = vfma(Ay, R[k], tI);
            const ull nI = vfma(Ax, I[k], tI);
            R[k] = nR; I[k] = nI;
        }
    } else if constexpr (BIT >= 1) {
        // register-pair-local wire: k-bit mask
        constexpr int mk = 1 << (BIT - 1);
        const ull a00x = bc(U00.x), a00y = bc(U00.y), n00y = bc(-U00.y);
        const ull a01x = bc(U01.x), a01y = bc(U01.y), n01y = bc(-U01.y);
        const ull a10x = bc(U10.x), a10y = bc(U10.y), n10y = bc(-U10.y);
        const ull a11x = bc(U11.x), a11y = bc(U11.y), n11y = bc(-U11.y);
        #pragma unroll
        for (int k = 0; k < 4; k++) {
            if ((k & mk) == 0) {
                const int k2 = k | mk;
                const ull R0 = R[k], I0 = I[k], R1 = R[k2], I1 = I[k2];
                // n0 = U00*s0 + U01*s1 ; n1 = U10*s0 + U11*s1
                R[k]  = vfma(a00x, R0, vfma(n00y, I0, vfma(a01x, R1, vmul(n01y, I1))));
                I[k]  = vfma(a00x, I0, vfma(a00y, R0, vfma(a01x, I1, vmul(a01y, R1))));
                R[k2] = vfma(a10x, R0, vfma(n10y, I0, vfma(a11x, R1, vmul(n11y, I1))));
                I[k2] = vfma(a10x, I0, vfma(a10y, R0, vfma(a11x, I1, vmul(a11y, R1))));
            }
        }
    } else {
        // within-vector wire (Q == 7): low half = bit0==0, high half = bit0==1.
        // new = (U00,U10)*even + (U01,U11)*odd  (per half)
        const ull c0x = pk(U00.x, U10.x), c0y = pk(U00.y, U10.y), n0y = pk(-U00.y, -U10.y);
        const ull c1x = pk(U01.x, U11.x), c1y = pk(U01.y, U11.y), n1y = pk(-U01.y, -U11.y);
        #pragma unroll
        for (int k = 0; k < 4; k++) {
            const ull ER = dup_lo(R[k]), EI = dup_lo(I[k]);
            const ull OR_ = dup_hi(R[k]), OI = dup_hi(I[k]);
            R[k] = vfma(c0x, ER, vfma(n0y, EI, vfma(c1x, OR_, vmul(n1y, OI))));
            I[k] = vfma(c0x, EI, vfma(c0y, ER, vfma(c1x, OI, vmul(c1y, OR_))));
        }
    }
}

// CNOT(control C, target T): where control bit == 1, flip target bit.
template<int C, int T>
__device__ __forceinline__ void apply_cnot(ull (&R)[4], ull (&I)[4], int lane) {
    constexpr int cb = 7 - C;  // control bit index
    constexpr int tb = 7 - T;  // target bit index
    if constexpr (cb >= 3 && tb >= 3) {
        // both lane bits: controlled lanes exchange with shfl partner
        const bool ctl = (lane >> (cb - 3)) & 1;
        #pragma unroll
        for (int k = 0; k < 4; k++) {
            const ull oR = shfl_u64<tb - 3>(R[k]);
            const ull oI = shfl_u64<tb - 3>(I[k]);
            R[k] = ctl ? oR : R[k];
            I[k] = ctl ? oI : I[k];
        }
    } else if constexpr (cb >= 3 && tb >= 1) {
        // control lane bit, target k-bit: controlled lanes swap register pairs
        const bool ctl = (lane >> (cb - 3)) & 1;
        constexpr int tm = 1 << (tb - 1);
        #pragma unroll
        for (int k = 0; k < 4; k++) {
            if ((k & tm) == 0) {
                const int k2 = k | tm;
                const ull aR = R[k], bR = R[k2], aI = I[k], bI = I[k2];
                R[k] = ctl ? bR : aR;  R[k2] = ctl ? aR : bR;
                I[k] = ctl ? bI : aI;  I[k2] = ctl ? aI : bI;
            }
        }
    } else if constexpr (cb >= 3) {
        // control lane bit, target vector-half: controlled lanes swap halves
        const bool ctl = (lane >> (cb - 3)) & 1;
        #pragma unroll
        for (int k = 0; k < 4; k++) {
            const ull sR = swap_h(R[k]), sI = swap_h(I[k]);
            R[k] = ctl ? sR : R[k];
            I[k] = ctl ? sI : I[k];
        }
    } else if constexpr (cb >= 1 && tb >= 3) {
        // control k-bit, target lane bit: regs with control bit set get shuffled
        constexpr int mk = 1 << (cb - 1);
        #pragma unroll
        for (int k = 0; k < 4; k++) {
            if (k & mk) {
                R[k] = shfl_u64<tb - 3>(R[k]);
                I[k] = shfl_u64<tb - 3>(I[k]);
            }
        }
    } else if constexpr (tb >= 3) {
        // control = vector-half bit (cb==0), target lane bit: shuffle high halves only
        #pragma unroll
        for (int k = 0; k < 4; k++) {
            float lo, hi;
            upk(R[k], lo, hi);
            hi = __shfl_xor_sync(0xffffffffu, hi, 1 << (tb - 3));
            R[k] = pk(lo, hi);
            upk(I[k], lo, hi);
            hi = __shfl_xor_sync(0xffffffffu, hi, 1 << (tb - 3));
            I[k] = pk(lo, hi);
        }
    } else if constexpr (cb >= 1 && tb >= 1) {
        // both k-bits: unconditional register permutation
        constexpr int mk = 1 << (cb - 1);
        constexpr int tm = 1 << (tb - 1);
        #pragma unroll
        for (int k = 0; k < 4; k++) {
            if ((k & mk) && ((k & tm) == 0)) {
                const int k2 = k | tm;
                ull t = R[k]; R[k] = R[k2]; R[k2] = t;
                t = I[k]; I[k] = I[k2]; I[k2] = t;
            }
        }
    } else if constexpr (cb >= 1) {
        // control k-bit, target vector-half (tb==0): swap halves where control set
        constexpr int mk = 1 << (cb - 1);
        #pragma unroll
        for (int k = 0; k < 4; k++) {
            if (k & mk) {
                R[k] = swap_h(R[k]);
                I[k] = swap_h(I[k]);
            }
        }
    } else {
        // control vector-half (cb==0), target k-bit: high halves swap across regs
        constexpr int tm = 1 << (tb - 1);
        #pragma unroll
        for (int k = 0; k < 4; k++) {
            if ((k & tm) == 0) {
                const int k2 = k | tm;
                float l0, h0, l1, h1;
                upk(R[k], l0, h0); upk(R[k2], l1, h1);
                R[k] = pk(l0, h1); R[k2] = pk(l1, h0);
                upk(I[k], l0, h0); upk(I[k2], l1, h1);
                I[k] = pk(l0, h1); I[k2] = pk(l1, h0);
            }
        }
    }
}

} // namespace

#define ROT_ALL(L) \
    apply_1q<0>(R, I, lane, &sU[L][0][0]); \
    apply_1q<1>(R, I, lane, &sU[L][1][0]); \
    apply_1q<2>(R, I, lane, &sU[L][2][0]); \
    apply_1q<3>(R, I, lane, &sU[L][3][0]); \
    apply_1q<4>(R, I, lane, &sU[L][4][0]); \
    apply_1q<5>(R, I, lane, &sU[L][5][0]); \
    apply_1q<6>(R, I, lane, &sU[L][6][0]); \
    apply_1q<7>(R, I, lane, &sU[L][7][0]);

#define CNOT_RING(Rr) \
    apply_cnot<0, (0 + Rr) & 7>(R, I, lane); \
    apply_cnot<1, (1 + Rr) & 7>(R, I, lane); \
    apply_cnot<2, (2 + Rr) & 7>(R, I, lane); \
    apply_cnot<3, (3 + Rr) & 7>(R, I, lane); \
    apply_cnot<4, (4 + Rr) & 7>(R, I, lane); \
    apply_cnot<5, (5 + Rr) & 7>(R, I, lane); \
    apply_cnot<6, (6 + Rr) & 7>(R, I, lane); \
    apply_cnot<7, (7 + Rr) & 7>(R, I, lane);

__global__ __launch_bounds__(256)
void qsim_kernel(const float* __restrict__ inputs,
                 const float* __restrict__ weights,
                 float* __restrict__ out, int B) {
    // Shared Rot matrices: Rot = RZ(omega) RY(theta) RZ(phi)
    __shared__ float2 sU[LAYERS][NQ][4];
    const int tid = threadIdx.x;
    if (tid < LAYERS * NQ) {
        const float* w = weights + tid * 3;
        float phi = w[0], th = w[1], om = w[2];
        float stv, ct;  sincosf(0.5f * th, &stv, &ct);
        float sa, ca;   sincosf(0.5f * (phi + om), &sa, &ca);  // ep = ca - i sa
        float sb, cb;   sincosf(0.5f * (phi - om), &sb, &cb);  // em = cb + i sb
        const int l = tid >> 3, q = tid & 7;
        sU[l][q][0] = make_float2( ca * ct, -sa * ct);   // U00 = ep*ct
        sU[l][q][1] = make_float2(-cb * stv, -sb * stv); // U01 = -em*st
        sU[l][q][2] = make_float2( cb * stv, -sb * stv); // U10 = conj(em)*st
        sU[l][q][3] = make_float2( ca * ct,  sa * ct);   // U11 = conj(ep)*ct
    }
    __syncthreads();

    const int wid = (int)((blockIdx.x * (unsigned)blockDim.x + tid) >> 5);
    if (wid >= B) return;
    const int lane = tid & 31;

    // ---- Build state directly after AngleEmbedding + layer-0 Rot column.
    // |0..0> is a product state and stays one under per-wire 1q gates:
    //   amp(i) = prod_q v_q[bit_q(i)],  v_q = Rot_q * RX_q(x) * |0>
    ull R[4], I[4];
    {
        float2 st[8];
        float2 P = make_float2(1.f, 0.f);
        float2 v5a, v5b, v6a, v6b, v7a, v7b;
        #pragma unroll
        for (int q = 0; q < 8; q++) {
            float x = inputs[(size_t)wid * 8 + q];
            float s, c;
            __sincosf(0.5f * x, &s, &c);
            // RX|0> = (c, -i s);  v0 = U00*c + U01*(-i s);  v1 = U10*c + U11*(-i s)
            const float2* U = &sU[0][q][0];
            float2 w0, w1;
            w0.x = fmaf(U[0].x, c,  U[1].y * s);
            w0.y = fmaf(U[0].y, c, -U[1].x * s);
            w1.x = fmaf(U[2].x, c,  U[3].y * s);
            w1.y = fmaf(U[2].y, c, -U[3].x * s);
            if (q < 5) {
                const bool b = (lane >> (4 - q)) & 1;
                float2 f;
                f.x = b ? w1.x : w0.x;
                f.y = b ? w1.y : w0.y;
                P = cmul(P, f);
            } else if (q == 5) { v5a = w0; v5b = w1; }
            else if (q == 6)   { v6a = w0; v6b = w1; }
            else               { v7a = w0; v7b = w1; }
        }
        float2 t0 = cmul(P, v5a), t1 = cmul(P, v5b);
        float2 u00 = cmul(t0, v6a), u01 = cmul(t0, v6b);
        float2 u10 = cmul(t1, v6a), u11 = cmul(t1, v6b);
        st[0] = cmul(u00, v7a); st[1] = cmul(u00, v7b);
        st[2] = cmul(u01, v7a); st[3] = cmul(u01, v7b);
        st[4] = cmul(u10, v7a); st[5] = cmul(u10, v7b);
        st[6] = cmul(u11, v7a); st[7] = cmul(u11, v7b);
        #pragma unroll
        for (int k = 0; k < 4; k++) {
            R[k] = pk(st[2 * k].x, st[2 * k + 1].x);
            I[k] = pk(st[2 * k].y, st[2 * k + 1].y);
        }
    }

    // ---- Layer 0 CNOT ring (rots already folded), then layers 1..5.
    CNOT_RING(1);
    ROT_ALL(1); CNOT_RING(2);
    ROT_ALL(2); CNOT_RING(3);
    ROT_ALL(3); CNOT_RING(4);
    ROT_ALL(4); CNOT_RING(5);
    ROT_ALL(5); CNOT_RING(6);

    // ---- <Z_q> : sign = +1 when wire-q bit of i is 0.
    float p[8];
    #pragma unroll
    for (int k = 0; k < 4; k++) {
        const ull P2 = vfma(R[k], R[k], vmul(I[k], I[k]));
        upk(P2, p[2 * k], p[2 * k + 1]);
    }
    const float tp = ((p[0] + p[1]) + (p[2] + p[3])) + ((p[4] + p[5]) + (p[6] + p[7]));

    float z[8];
    #pragma unroll
    for (int q = 0; q < 5; q++) z[q] = ((lane >> (4 - q)) & 1) ? -tp : tp;
    z[5] = 0.f; z[6] = 0.f; z[7] = 0.f;
    #pragma unroll
    for (int j = 0; j < 8; j++) {
        z[5] += ((j >> 2) & 1) ? -p[j] : p[j];
        z[6] += ((j >> 1) & 1) ? -p[j] : p[j];
        z[7] += ((j     ) & 1) ? -p[j] : p[j];
    }
    #pragma unroll
    for (int s = 16; s >= 1; s >>= 1) {
        #pragma unroll
        for (int q = 0; q < 8; q++) z[q] += __shfl_xor_sync(0xffffffffu, z[q], s);
    }
    if (lane == 0) {
        float4* o = reinterpret_cast<float4*>(out + (size_t)wid * 8);
        o[0] = make_float4(z[0], z[1], z[2], z[3]);
        o[1] = make_float4(z[4], z[5], z[6], z[7]);
    }
}

extern "C" void kernel_launch(void* const* d_in, const int* in_sizes, int n_in,
                              void* d_out, int out_size) {
    const float* inputs  = (const float*)d_in[0];   // (B, 8) float32
    const float* weights = (const float*)d_in[1];   // (6, 8, 3) float32
    float* out = (float*)d_out;                     // (B, 8) float32
    const int B = in_sizes[0] / 8;
    const int threads = 256;
    const int blocks = (B * 32 + threads - 1) / threads;
    qsim_kernel<<<blocks, threads>>>(inputs, weights, out, B);
}

// round 16
// speedup vs baseline: 1.0013x; 1.0013x over previous
#include <cuda_runtime.h>

// 8-qubit statevector simulator, one warp per batch element.
// State: 256 complex amplitudes = 8 complex per lane, stored SoA-packed:
//   R[4], I[4] are f32x2 (64-bit) registers; R[k] = (re[2k], re[2k+1]).
// Global amplitude index i = lane*8 + j  (wire q <-> bit (7-q) of i):
//   wires 0..4 -> lane bits 4..0 (cross-lane, via shfl.xor)
//   wires 5,6  -> packed-register index bits 1,0 (k bits)
//   wire 7     -> low/high half of the f32x2 vector
// Gate math uses fma.rn.f32x2. Coefficients stored as float4 pairs
// g[0]=(U00.x,U00.y,U01.x,U01.y), g[1]=(U11.x,U11.y,U10.x,U10.y) so
// cross-lane gates fetch (A,B) with a single LDS.128 selected by lane bit.

namespace {

constexpr int NQ = 8;
constexpr int LAYERS = 6;
using ull = unsigned long long;

__device__ __forceinline__ ull pk(float lo, float hi) {
    ull r;
    asm("mov.b64 %0, {%1, %2};" : "=l"(r) : "r"(__float_as_uint(lo)), "r"(__float_as_uint(hi)));
    return r;
}
__device__ __forceinline__ void upk(ull v, float& lo, float& hi) {
    unsigned ul, uh;
    asm("mov.b64 {%0, %1}, %2;" : "=r"(ul), "=r"(uh) : "l"(v));
    lo = __uint_as_float(ul); hi = __uint_as_float(uh);
}
__device__ __forceinline__ ull bc(float s) { return pk(s, s); }
__device__ __forceinline__ ull vfma(ull a, ull b, ull c) {
    ull d;
    asm("fma.rn.f32x2 %0, %1, %2, %3;" : "=l"(d) : "l"(a), "l"(b), "l"(c));
    return d;
}
__device__ __forceinline__ ull vmul(ull a, ull b) {
    ull d;
    asm("mul.rn.f32x2 %0, %1, %2;" : "=l"(d) : "l"(a), "l"(b));
    return d;
}
template<int LB>
__device__ __forceinline__ ull shfl_u64(ull v) {
    float lo, hi; upk(v, lo, hi);
    lo = __shfl_xor_sync(0xffffffffu, lo, 1 << LB);
    hi = __shfl_xor_sync(0xffffffffu, hi, 1 << LB);
    return pk(lo, hi);
}
__device__ __forceinline__ ull dup_lo(ull v) { float lo, hi; upk(v, lo, hi); return pk(lo, lo); }
__device__ __forceinline__ ull dup_hi(ull v) { float lo, hi; upk(v, lo, hi); return pk(hi, hi); }
__device__ __forceinline__ ull swap_h(ull v) { float lo, hi; upk(v, lo, hi); return pk(hi, lo); }

__device__ __forceinline__ float2 cmul(float2 a, float2 b) {
    return make_float2(fmaf(a.x, b.x, -a.y * b.y), fmaf(a.x, b.y, a.y * b.x));
}

// Generic shared 2x2 gate on wire Q, packed state.
// g[0] = (U00.x, U00.y, U01.x, U01.y); g[1] = (U11.x, U11.y, U10.x, U10.y).
template<int Q>
__device__ __forceinline__ void apply_1q(ull (&R)[4], ull (&I)[4], int lane,
                                         const float4* __restrict__ g) {
    constexpr int BIT = 7 - Q;
    if constexpr (BIT >= 3) {
        // cross-lane wire (lane bit LB). new = A*mine + B*other
        constexpr int LB = BIT - 3;
        const int b = (lane >> LB) & 1;
        const float4 f = g[b];           // one LDS.128: A=(f.x,f.y), B=(f.z,f.w)
        const ull Ax = bc(f.x), Ay = bc(f.y), nAy = bc(-f.y);
        const ull Bx = bc(f.z), By = bc(f.w), nBy = bc(-f.w);
        #pragma unroll
        for (int k = 0; k < 4; k++) {
            const ull oR = shfl_u64<LB>(R[k]);
            const ull oI = shfl_u64<LB>(I[k]);
            // n.re = A.x*s.re - A.y*s.im + B.x*o.re - B.y*o.im
            ull tR = vfma(Bx, oR, vmul(nBy, oI));
            tR = vfma(nAy, I[k], tR);
            const ull nR = vfma(Ax, R[k], tR);
            // n.im = A.x*s.im + A.y*s.re + B.x*o.im + B.y*o.re
            ull tI = vfma(Bx, oI, vmul(By, oR));
            tI = vfma(Ay, R[k], tI);
            const ull nI = vfma(Ax, I[k], tI);
            R[k] = nR; I[k] = nI;
        }
    } else if constexpr (BIT >= 1) {
        // register-pair-local wire: k-bit mask
        constexpr int mk = 1 << (BIT - 1);
        const float4 f0 = g[0], f1 = g[1];
        // U00=(f0.x,f0.y) U01=(f0.z,f0.w) U11=(f1.x,f1.y) U10=(f1.z,f1.w)
        const ull a00x = bc(f0.x), a00y = bc(f0.y), n00y = bc(-f0.y);
        const ull a01x = bc(f0.z), a01y = bc(f0.w), n01y = bc(-f0.w);
        const ull a10x = bc(f1.z), a10y = bc(f1.w), n10y = bc(-f1.w);
        const ull a11x = bc(f1.x), a11y = bc(f1.y), n11y = bc(-f1.y);
        #pragma unroll
        for (int k = 0; k < 4; k++) {
            if ((k & mk) == 0) {
                const int k2 = k | mk;
                const ull R0 = R[k], I0 = I[k], R1 = R[k2], I1 = I[k2];
                // n0 = U00*s0 + U01*s1 ; n1 = U10*s0 + U11*s1
                R[k]  = vfma(a00x, R0, vfma(n00y, I0, vfma(a01x, R1, vmul(n01y, I1))));
                I[k]  = vfma(a00x, I0, vfma(a00y, R0, vfma(a01x, I1, vmul(a01y, R1))));
                R[k2] = vfma(a10x, R0, vfma(n10y, I0, vfma(a11x, R1, vmul(n11y, I1))));
                I[k2] = vfma(a10x, I0, vfma(a10y, R0, vfma(a11x, I1, vmul(a11y, R1))));
            }
        }
    } else {
        // within-vector wire (Q == 7): low half = bit0==0, high half = bit0==1.
        // new = (U00,U10)*even + (U01,U11)*odd  (per half)
        const float4 f0 = g[0], f1 = g[1];
        const ull c0x = pk(f0.x, f1.z), c0y = pk(f0.y, f1.w), n0y = pk(-f0.y, -f1.w);
        const ull c1x = pk(f0.z, f1.x), c1y = pk(f0.w, f1.y), n1y = pk(-f0.w, -f1.y);
        #pragma unroll
        for (int k = 0; k < 4; k++) {
            const ull ER = dup_lo(R[k]), EI = dup_lo(I[k]);
            const ull OR_ = dup_hi(R[k]), OI = dup_hi(I[k]);
            R[k] = vfma(c0x, ER, vfma(n0y, EI, vfma(c1x, OR_, vmul(n1y, OI))));
            I[k] = vfma(c0x, EI, vfma(c0y, ER, vfma(c1x, OI, vmul(c1y, OR_))));
        }
    }
}

// CNOT(control C, target T): where control bit == 1, flip target bit.
template<int C, int T>
__device__ __forceinline__ void apply_cnot(ull (&R)[4], ull (&I)[4], int lane) {
    constexpr int cb = 7 - C;  // control bit index
    constexpr int tb = 7 - T;  // target bit index
    if constexpr (cb >= 3 && tb >= 3) {
        // both lane bits: controlled lanes exchange with shfl partner
        const bool ctl = (lane >> (cb - 3)) & 1;
        #pragma unroll
        for (int k = 0; k < 4; k++) {
            const ull oR = shfl_u64<tb - 3>(R[k]);
            const ull oI = shfl_u64<tb - 3>(I[k]);
            R[k] = ctl ? oR : R[k];
            I[k] = ctl ? oI : I[k];
        }
    } else if constexpr (cb >= 3 && tb >= 1) {
        // control lane bit, target k-bit: controlled lanes swap register pairs
        const bool ctl = (lane >> (cb - 3)) & 1;
        constexpr int tm = 1 << (tb - 1);
        #pragma unroll
        for (int k = 0; k < 4; k++) {
            if ((k & tm) == 0) {
                const int k2 = k | tm;
                const ull aR = R[k], bR = R[k2], aI = I[k], bI = I[k2];
                R[k] = ctl ? bR : aR;  R[k2] = ctl ? aR : bR;
                I[k] = ctl ? bI : aI;  I[k2] = ctl ? aI : bI;
            }
        }
    } else if constexpr (cb >= 3) {
        // control lane bit, target vector-half: controlled lanes swap halves
        const bool ctl = (lane >> (cb - 3)) & 1;
        #pragma unroll
        for (int k = 0; k < 4; k++) {
            const ull sR = swap_h(R[k]), sI = swap_h(I[k]);
            R[k] = ctl ? sR : R[k];
            I[k] = ctl ? sI : I[k];
        }
    } else if constexpr (cb >= 1 && tb >= 3) {
        // control k-bit, target lane bit: regs with control bit set get shuffled
        constexpr int mk = 1 << (cb - 1);
        #pragma unroll
        for (int k = 0; k < 4; k++) {
            if (k & mk) {
                R[k] = shfl_u64<tb - 3>(R[k]);
                I[k] = shfl_u64<tb - 3>(I[k]);
            }
        }
    } else if constexpr (tb >= 3) {
        // control = vector-half bit (cb==0), target lane bit: shuffle high halves only
        #pragma unroll
        for (int k = 0; k < 4; k++) {
            float lo, hi;
            upk(R[k], lo, hi);
            hi = __shfl_xor_sync(0xffffffffu, hi, 1 << (tb - 3));
            R[k] = pk(lo, hi);
            upk(I[k], lo, hi);
            hi = __shfl_xor_sync(0xffffffffu, hi, 1 << (tb - 3));
            I[k] = pk(lo, hi);
        }
    } else if constexpr (cb >= 1 && tb >= 1) {
        // both k-bits: unconditional register permutation
        constexpr int mk = 1 << (cb - 1);
        constexpr int tm = 1 << (tb - 1);
        #pragma unroll
        for (int k = 0; k < 4; k++) {
            if ((k & mk) && ((k & tm) == 0)) {
                const int k2 = k | tm;
                ull t = R[k]; R[k] = R[k2]; R[k2] = t;
                t = I[k]; I[k] = I[k2]; I[k2] = t;
            }
        }
    } else if constexpr (cb >= 1) {
        // control k-bit, target vector-half (tb==0): swap halves where control set
        constexpr int mk = 1 << (cb - 1);
        #pragma unroll
        for (int k = 0; k < 4; k++) {
            if (k & mk) {
                R[k] = swap_h(R[k]);
                I[k] = swap_h(I[k]);
            }
        }
    } else {
        // control vector-half (cb==0), target k-bit: high halves swap across regs
        constexpr int tm = 1 << (tb - 1);
        #pragma unroll
        for (int k = 0; k < 4; k++) {
            if ((k & tm) == 0) {
                const int k2 = k | tm;
                float l0, h0, l1, h1;
                upk(R[k], l0, h0); upk(R[k2], l1, h1);
                R[k] = pk(l0, h1); R[k2] = pk(l1, h0);
                upk(I[k], l0, h0); upk(I[k2], l1, h1);
                I[k] = pk(l0, h1); I[k2] = pk(l1, h0);
            }
        }
    }
}

} // namespace

#define ROT_ALL(L) \
    apply_1q<0>(R, I, lane, sU4[L][0]); \
    apply_1q<1>(R, I, lane, sU4[L][1]); \
    apply_1q<2>(R, I, lane, sU4[L][2]); \
    apply_1q<3>(R, I, lane, sU4[L][3]); \
    apply_1q<4>(R, I, lane, sU4[L][4]); \
    apply_1q<5>(R, I, lane, sU4[L][5]); \
    apply_1q<6>(R, I, lane, sU4[L][6]); \
    apply_1q<7>(R, I, lane, sU4[L][7]);

#define CNOT_RING(Rr) \
    apply_cnot<0, (0 + Rr) & 7>(R, I, lane); \
    apply_cnot<1, (1 + Rr) & 7>(R, I, lane); \
    apply_cnot<2, (2 + Rr) & 7>(R, I, lane); \
    apply_cnot<3, (3 + Rr) & 7>(R, I, lane); \
    apply_cnot<4, (4 + Rr) & 7>(R, I, lane); \
    apply_cnot<5, (5 + Rr) & 7>(R, I, lane); \
    apply_cnot<6, (6 + Rr) & 7>(R, I, lane); \
    apply_cnot<7, (7 + Rr) & 7>(R, I, lane);

__global__ __launch_bounds__(256, 6)
void qsim_kernel(const float* __restrict__ inputs,
                 const float* __restrict__ weights,
                 float* __restrict__ out, int B) {
    // Shared Rot matrices: Rot = RZ(omega) RY(theta) RZ(phi)
    // sU4[l][q][0] = (U00.x, U00.y, U01.x, U01.y)
    // sU4[l][q][1] = (U11.x, U11.y, U10.x, U10.y)
    __shared__ float4 sU4[LAYERS][NQ][2];
    const int tid = threadIdx.x;
    if (tid < LAYERS * NQ) {
        const float* w = weights + tid * 3;
        float phi = w[0], th = w[1], om = w[2];
        float stv, ct;  sincosf(0.5f * th, &stv, &ct);
        float sa, ca;   sincosf(0.5f * (phi + om), &sa, &ca);  // ep = ca - i sa
        float sb, cb;   sincosf(0.5f * (phi - om), &sb, &cb);  // em = cb + i sb
        const int l = tid >> 3, q = tid & 7;
        // U00 = ep*ct; U01 = -em*st; U10 = conj(em)*st; U11 = conj(ep)*ct
        sU4[l][q][0] = make_float4( ca * ct, -sa * ct, -cb * stv, -sb * stv);
        sU4[l][q][1] = make_float4( ca * ct,  sa * ct,  cb * stv, -sb * stv);
    }
    __syncthreads();

    const int wid = (int)((blockIdx.x * (unsigned)blockDim.x + tid) >> 5);
    if (wid >= B) return;
    const int lane = tid & 31;

    // ---- Build state directly after AngleEmbedding + layer-0 Rot column.
    // |0..0> is a product state and stays one under per-wire 1q gates:
    //   amp(i) = prod_q v_q[bit_q(i)],  v_q = Rot_q * RX_q(x) * |0>
    ull R[4], I[4];
    {
        float2 st[8];
        float2 P = make_float2(1.f, 0.f);
        float2 v5a, v5b, v6a, v6b, v7a, v7b;
        #pragma unroll
        for (int q = 0; q < 8; q++) {
            float x = inputs[(size_t)wid * 8 + q];
            float s, c;
            __sincosf(0.5f * x, &s, &c);
            // RX|0> = (c, -i s);  v0 = U00*c + U01*(-i s);  v1 = U10*c + U11*(-i s)
            const float4 f0 = sU4[0][q][0];   // (U00.x,U00.y,U01.x,U01.y)
            const float4 f1 = sU4[0][q][1];   // (U11.x,U11.y,U10.x,U10.y)
            float2 w0, w1;
            w0.x = fmaf(f0.x, c,  f0.w * s);   // U00.x*c + U01.y*s
            w0.y = fmaf(f0.y, c, -f0.z * s);   // U00.y*c - U01.x*s
            w1.x = fmaf(f1.z, c,  f1.y * s);   // U10.x*c + U11.y*s
            w1.y = fmaf(f1.w, c, -f1.x * s);   // U10.y*c - U11.x*s
            if (q < 5) {
                const bool b = (lane >> (4 - q)) & 1;
                float2 f;
                f.x = b ? w1.x : w0.x;
                f.y = b ? w1.y : w0.y;
                P = cmul(P, f);
            } else if (q == 5) { v5a = w0; v5b = w1; }
            else if (q == 6)   { v6a = w0; v6b = w1; }
            else               { v7a = w0; v7b = w1; }
        }
        float2 t0 = cmul(P, v5a), t1 = cmul(P, v5b);
        float2 u00 = cmul(t0, v6a), u01 = cmul(t0, v6b);
        float2 u10 = cmul(t1, v6a), u11 = cmul(t1, v6b);
        st[0] = cmul(u00, v7a); st[1] = cmul(u00, v7b);
        st[2] = cmul(u01, v7a); st[3] = cmul(u01, v7b);
        st[4] = cmul(u10, v7a); st[5] = cmul(u10, v7b);
        st[6] = cmul(u11, v7a); st[7] = cmul(u11, v7b);
        #pragma unroll
        for (int k = 0; k < 4; k++) {
            R[k] = pk(st[2 * k].x, st[2 * k + 1].x);
            I[k] = pk(st[2 * k].y, st[2 * k + 1].y);
        }
    }

    // ---- Layer 0 CNOT ring (rots already folded), then layers 1..5.
    CNOT_RING(1);
    ROT_ALL(1); CNOT_RING(2);
    ROT_ALL(2); CNOT_RING(3);
    ROT_ALL(3); CNOT_RING(4);
    ROT_ALL(4); CNOT_RING(5);
    ROT_ALL(5); CNOT_RING(6);

    // ---- <Z_q> : sign = +1 when wire-q bit of i is 0.
    float p[8];
    #pragma unroll
    for (int k = 0; k < 4; k++) {
        const ull P2 = vfma(R[k], R[k], vmul(I[k], I[k]));
        upk(P2, p[2 * k], p[2 * k + 1]);
    }
    const float tp = ((p[0] + p[1]) + (p[2] + p[3])) + ((p[4] + p[5]) + (p[6] + p[7]));

    // Locally-signed sums for wires 5..7 (local bits 2,1,0 of j).
    float s5 = 0.f, s6 = 0.f, s7 = 0.f;
    #pragma unroll
    for (int j = 0; j < 8; j++) {
        s5 += ((j >> 2) & 1) ? -p[j] : p[j];
        s6 += ((j >> 1) & 1) ? -p[j] : p[j];
        s7 += ((j     ) & 1) ? -p[j] : p[j];
    }

    // Signed Walsh-Hadamard butterfly on tp: after 5 steps, lane m holds
    // sum_p (-1)^{popc(m & p_lane)} tp(p). Lane (1<<(4-q)) holds z_q, q=0..4.
    float v = tp;
    #pragma unroll
    for (int b = 4; b >= 0; b--) {
        const float o = __shfl_xor_sync(0xffffffffu, v, 1 << b);
        v = ((lane >> b) & 1) ? (o - v) : (o + v);
    }
    // Plain butterflies for s5..s7 (every lane ends with the warp total).
    #pragma unroll
    for (int sft = 16; sft >= 1; sft >>= 1) {
        s5 += __shfl_xor_sync(0xffffffffu, s5, sft);
        s6 += __shfl_xor_sync(0xffffffffu, s6, sft);
        s7 += __shfl_xor_sync(0xffffffffu, s7, sft);
    }

    float* o = out + (size_t)wid * 8;
    if (lane == 16) o[0] = v;
    if (lane == 8)  o[1] = v;
    if (lane == 4)  o[2] = v;
    if (lane == 2)  o[3] = v;
    if (lane == 1)  o[4] = v;
    if (lane == 0) { o[5] = s5; o[6] = s6; o[7] = s7; }
}

extern "C" void kernel_launch(void* const* d_in, const int* in_sizes, int n_in,
                              void* d_out, int out_size) {
    const float* inputs  = (const float*)d_in[0];   // (B, 8) float32
    const float* weights = (const float*)d_in[1];   // (6, 8, 3) float32
    float* out = (float*)d_out;                     // (B, 8) float32
    const int B = in_sizes[0] / 8;
    const int threads = 256;
    const int blocks = (B * 32 + threads - 1) / threads;
    qsim_kernel<<<blocks, threads>>>(inputs, weights, out, B);
}